// round 9
// baseline (speedup 1.0000x reference)
#include <cuda_runtime.h>
#include <cstdint>

// Row layout: [x, y, w, h, obj_conf, cls_0 .. cls_79]  (85 floats per row)
// Outputs: detections [total,7] fp32, then valid [total] (fp32 1/0 or uint8).

#define ROW_LEN 85
#define CONF_THRES 0.05f

#define CHUNK_ROWS 32                        // rows per ring stage (8 warps x 4)
#define RING_D 3                             // ring depth
#define CHUNK_FLOATS (CHUNK_ROWS * ROW_LEN)  // 2720
#define CHUNK_BYTES (CHUNK_FLOATS * 4)       // 10880 (mult of 16)

#define PERSISTENT_BLOCKS 1064               // ~7 blocks/SM on 152 SMs

__device__ __forceinline__ unsigned smem_u32(const void* p) {
    unsigned a;
    asm("{ .reg .u64 t; cvta.to.shared.u64 t, %1; cvt.u32.u64 %0, t; }"
        : "=r"(a) : "l"(p));
    return a;
}

__device__ __forceinline__ void mbar_wait_parity(unsigned addr, unsigned parity) {
    asm volatile(
        "{\n\t"
        ".reg .pred P;\n\t"
        "WAIT_%=: \n\t"
        "mbarrier.try_wait.parity.acquire.cta.shared::cta.b64 P, [%0], %1, 0x989680;\n\t"
        "@P bra.uni DONE_%=;\n\t"
        "bra.uni WAIT_%=;\n\t"
        "DONE_%=:\n\t"
        "}"
        :: "r"(addr), "r"(parity) : "memory");
}

// Scan 85 floats of one row (strided by 8 over 8 lanes), return per-lane
// (e0, max m, winning class index). Proven R3..R7 semantics.
template <typename LoadF>
__device__ __forceinline__ void scan_row(LoadF ld, int sub,
                                         float& e0, float& m, unsigned& mi) {
    e0 = ld(sub);
    m  = (sub >= 5) ? e0 : -1e30f;     // classes 0..2 live in lanes 5..7
    int wk = 0;
    #pragma unroll
    for (int k = 1; k < 10; k++) {
        float v = ld(sub + 8 * k);
        if (v > m) { m = v; wk = k; }
    }
    if (sub < ROW_LEN - 80) {          // elems 80..84
        float v = ld(sub + 80);
        if (v > m) { m = v; wk = 10; }
    }
    mi = (unsigned)(sub - 5 + 8 * wk);
}

// Group reduction + output write for one row. gmask/conf logic proven R3..R7.
__device__ __forceinline__ void reduce_and_store(
    float e0, float m, unsigned mi, int lane, int sub, long long r,
    float* __restrict__ det, float* __restrict__ valid_f,
    uint8_t* __restrict__ valid_b, bool wvalid)
{
    const unsigned gmask = 0xFFu << (lane & 24);
    const unsigned mb    = __float_as_uint(m);
    const unsigned maxb  = __reduce_max_sync(gmask, mb);
    const unsigned cand  = (mb == maxb) ? mi : 0xFFFFFFFFu;
    const unsigned gidx  = __reduce_min_sync(gmask, cand);

    const float conf = __shfl_sync(0xFFFFFFFFu, e0, (lane & 24) | 4);
    const float vf   = (conf >= CONF_THRES) ? 1.0f : 0.0f;

    if (wvalid) {
        if (sub < 7) {
            float outv;
            if (sub < 5)       outv = e0 * vf;
            else if (sub == 5) outv = __uint_as_float(maxb) * vf;
            else               outv = (float)gidx * vf;
            det[r * 7 + sub] = outv;
        } else {
            if (valid_f) valid_f[r] = vf;
            else         valid_b[r] = (vf != 0.0f) ? 1 : 0;
        }
    }
}

__global__ __launch_bounds__(256) void postproc_kernel(
    const float* __restrict__ pred,
    float* __restrict__ det,          // [total, 7]
    float* __restrict__ valid_f,      // [total] if float mode, else nullptr
    uint8_t* __restrict__ valid_b,    // [total] if bool mode, else nullptr
    int total,
    int numFull)                      // number of full 32-row chunks
{
    __shared__ float sbuf[RING_D][CHUNK_FLOATS];
    __shared__ __align__(8) unsigned long long mbar[RING_D];

    const int tid  = threadIdx.x;
    const int lane = tid & 31;
    const int wid  = tid >> 5;
    const int sub  = lane & 7;
    const int grp  = lane >> 3;

    // Bank-conflict-free row mapping within a chunk (row delta 8 between the
    // warp's 4 groups -> groups tile all 32 smem banks).
    const int rowInChunk = wid + 8 * grp;

    const int bid  = blockIdx.x;
    const int grid = gridDim.x;

    // Chunks for this block: c = bid + k*grid, k = 0..myChunks-1
    const int myChunks = (numFull > bid) ? (numFull - bid + grid - 1) / grid : 0;

    if (myChunks > 0) {
        if (tid == 0) {
            #pragma unroll
            for (int s = 0; s < RING_D; s++) {
                asm volatile("mbarrier.init.shared.b64 [%0], %1;"
                             :: "r"(smem_u32(&mbar[s])), "r"(1u) : "memory");
            }
        }
        __syncthreads();
        asm volatile("fence.proxy.async.shared::cta;" ::: "memory");

        // Prologue: fill the ring.
        if (tid == 0) {
            const int pre = myChunks < RING_D ? myChunks : RING_D;
            for (int k = 0; k < pre; k++) {
                const long long c = bid + (long long)k * grid;
                asm volatile(
                    "mbarrier.arrive.expect_tx.shared.b64 _, [%0], %1;"
                    :: "r"(smem_u32(&mbar[k])), "r"((unsigned)CHUNK_BYTES)
                    : "memory");
                asm volatile(
                    "cp.async.bulk.shared::cta.global.mbarrier::complete_tx::bytes "
                    "[%0], [%1], %2, [%3];"
                    :: "r"(smem_u32(&sbuf[k][0])),
                       "l"((const char*)(pred + c * CHUNK_ROWS * ROW_LEN)),
                       "r"((unsigned)CHUNK_BYTES),
                       "r"(smem_u32(&mbar[k])) : "memory");
            }
        }

        int s = 0, fph = 0;
        for (int k = 0; k < myChunks; k++) {
            mbar_wait_parity(smem_u32(&mbar[s]), (unsigned)fph);

            const long long c = bid + (long long)k * grid;
            const long long r = c * CHUNK_ROWS + rowInChunk;

            const float* srow = &sbuf[s][rowInChunk * ROW_LEN];
            float e0, m; unsigned mi;
            scan_row([&](int i) { return srow[i]; }, sub, e0, m, mi);
            reduce_and_store(e0, m, mi, lane, sub, r, det, valid_f, valid_b, true);

            __syncthreads();   // all 8 warps done with sbuf[s]

            if (tid == 0 && k + RING_D < myChunks) {
                const long long c2 = c + (long long)RING_D * grid;
                asm volatile(
                    "mbarrier.arrive.expect_tx.shared.b64 _, [%0], %1;"
                    :: "r"(smem_u32(&mbar[s])), "r"((unsigned)CHUNK_BYTES)
                    : "memory");
                asm volatile(
                    "cp.async.bulk.shared::cta.global.mbarrier::complete_tx::bytes "
                    "[%0], [%1], %2, [%3];"
                    :: "r"(smem_u32(&sbuf[s][0])),
                       "l"((const char*)(pred + c2 * CHUNK_ROWS * ROW_LEN)),
                       "r"((unsigned)CHUNK_BYTES),
                       "r"(smem_u32(&mbar[s])) : "memory");
            }
            if (++s == RING_D) { s = 0; fph ^= 1; }
        }
    }

    // Tail rows (total % 32): handled by block 0 via direct LDG.
    if (bid == 0) {
        const long long tail0 = (long long)numFull * CHUNK_ROWS;
        if (tail0 < (long long)total) {
            const long long r = tail0 + rowInChunk;     // up to 32 rows
            const bool wvalid = (r < (long long)total);
            const long long rr = wvalid ? r : (long long)(total - 1);
            const float* row = pred + rr * ROW_LEN;

            float e0, m; unsigned mi;
            scan_row([&](int i) { return row[i]; }, sub, e0, m, mi);
            reduce_and_store(e0, m, mi, lane, sub, r, det, valid_f, valid_b, wvalid);
        }
    }
}

extern "C" void kernel_launch(void* const* d_in, const int* in_sizes, int n_in,
                              void* d_out, int out_size)
{
    const float* pred = (const float*)d_in[0];
    const int total = in_sizes[0] / ROW_LEN;   // B*N rows
    const int numFull = total / CHUNK_ROWS;

    float* det = (float*)d_out;
    float* valid_f = nullptr;
    uint8_t* valid_b = nullptr;
    if (out_size == total * 8) {
        valid_f = det + (long long)total * 7;      // valid as 1.0/0.0 floats
    } else {
        valid_b = (uint8_t*)(det + (long long)total * 7);  // valid as bytes
    }

    int blocks = PERSISTENT_BLOCKS;
    if (numFull > 0 && numFull < blocks) blocks = numFull;
    if (blocks < 1) blocks = 1;
    postproc_kernel<<<blocks, 256>>>(pred, det, valid_f, valid_b, total, numFull);
}

// round 10
// speedup vs baseline: 1.1912x; 1.1912x over previous
#include <cuda_runtime.h>
#include <cstdint>

// Row layout: [x, y, w, h, obj_conf, cls_0 .. cls_79]  (85 floats per row)
// Outputs: detections [total,7] fp32, then valid [total] (fp32 1/0 or uint8).

#define ROW_LEN 85
#define CONF_THRES 0.05f

#define CHUNK_ROWS 32                        // rows per ring stage (8 warps x 4)
#define RING_D 2                             // ring depth (22KB smem -> 8 blk/SM)
#define CHUNK_FLOATS (CHUNK_ROWS * ROW_LEN)  // 2720
#define CHUNK_BYTES (CHUNK_FLOATS * 4)       // 10880 (mult of 16)

#define PERSIST_BLOCKS 1216                  // 8 blocks/SM x 152 SMs: one wave

__device__ __forceinline__ unsigned smem_u32(const void* p) {
    unsigned a;
    asm("{ .reg .u64 t; cvta.to.shared.u64 t, %1; cvt.u32.u64 %0, t; }"
        : "=r"(a) : "l"(p));
    return a;
}

__device__ __forceinline__ void mbar_wait_parity(unsigned addr, unsigned parity) {
    asm volatile(
        "{\n\t"
        ".reg .pred P;\n\t"
        "WAIT_%=: \n\t"
        "mbarrier.try_wait.parity.acquire.cta.shared::cta.b64 P, [%0], %1, 0x989680;\n\t"
        "@P bra.uni DONE_%=;\n\t"
        "bra.uni WAIT_%=;\n\t"
        "DONE_%=:\n\t"
        "}"
        :: "r"(addr), "r"(parity) : "memory");
}

// Scan 85 floats of one row (strided by 8 over 8 lanes), return per-lane
// (e0, max m, winning class index). Proven R3..R7 semantics.
template <typename LoadF>
__device__ __forceinline__ void scan_row(LoadF ld, int sub,
                                         float& e0, float& m, unsigned& mi) {
    e0 = ld(sub);
    m  = (sub >= 5) ? e0 : -1e30f;     // classes 0..2 live in lanes 5..7
    int wk = 0;
    #pragma unroll
    for (int k = 1; k < 10; k++) {
        float v = ld(sub + 8 * k);
        if (v > m) { m = v; wk = k; }
    }
    if (sub < ROW_LEN - 80) {          // elems 80..84
        float v = ld(sub + 80);
        if (v > m) { m = v; wk = 10; }
    }
    mi = (unsigned)(sub - 5 + 8 * wk);
}

// Group reduction + output write for one row (proven R3..R7 logic).
__device__ __forceinline__ void reduce_and_store(
    float e0, float m, unsigned mi, int lane, int sub, long long r,
    float* __restrict__ det, float* __restrict__ valid_f,
    uint8_t* __restrict__ valid_b, bool wvalid)
{
    const unsigned gmask = 0xFFu << (lane & 24);
    const unsigned mb    = __float_as_uint(m);
    const unsigned maxb  = __reduce_max_sync(gmask, mb);
    const unsigned cand  = (mb == maxb) ? mi : 0xFFFFFFFFu;
    const unsigned gidx  = __reduce_min_sync(gmask, cand);

    const float conf = __shfl_sync(0xFFFFFFFFu, e0, (lane & 24) | 4);
    const float vf   = (conf >= CONF_THRES) ? 1.0f : 0.0f;

    if (wvalid) {
        if (sub < 7) {
            float outv;
            if (sub < 5)       outv = e0 * vf;
            else if (sub == 5) outv = __uint_as_float(maxb) * vf;
            else               outv = (float)gidx * vf;
            det[r * 7 + sub] = outv;
        } else {
            if (valid_f) valid_f[r] = vf;
            else         valid_b[r] = (vf != 0.0f) ? 1 : 0;
        }
    }
}

__global__ __launch_bounds__(256) void postproc_kernel(
    const float* __restrict__ pred,
    float* __restrict__ det,
    float* __restrict__ valid_f,
    uint8_t* __restrict__ valid_b,
    int total,
    int numFull)                      // number of full 32-row chunks
{
    __shared__ float sbuf[RING_D][CHUNK_FLOATS];
    __shared__ __align__(8) unsigned long long mbar[RING_D];

    const int tid  = threadIdx.x;
    const int lane = tid & 31;
    const int wid  = tid >> 5;
    const int sub  = lane & 7;
    const int grp  = lane >> 3;

    // Bank-conflict-free row mapping within a chunk (row delta 8 between the
    // warp's 4 groups -> groups tile all 32 smem banks).
    const int rowInChunk = wid + 8 * grp;

    const int bid  = blockIdx.x;
    const int grid = gridDim.x;

    // Contiguous chunk range per block: first `rem` blocks get base+1 chunks.
    const int base = numFull / grid;
    const int rem  = numFull % grid;
    const int myCount = base + (bid < rem ? 1 : 0);
    const long long myStart = (long long)bid * base + (bid < rem ? bid : rem);

    if (myCount > 0) {
        if (tid == 0) {
            #pragma unroll
            for (int s = 0; s < RING_D; s++) {
                asm volatile("mbarrier.init.shared.b64 [%0], %1;"
                             :: "r"(smem_u32(&mbar[s])), "r"(1u) : "memory");
            }
        }
        __syncthreads();
        asm volatile("fence.proxy.async.shared::cta;" ::: "memory");

        // Prologue: fill the ring with the first RING_D chunks.
        if (tid == 0) {
            const int pre = myCount < RING_D ? myCount : RING_D;
            for (int k = 0; k < pre; k++) {
                const long long c = myStart + k;
                asm volatile(
                    "mbarrier.arrive.expect_tx.shared.b64 _, [%0], %1;"
                    :: "r"(smem_u32(&mbar[k])), "r"((unsigned)CHUNK_BYTES)
                    : "memory");
                asm volatile(
                    "cp.async.bulk.shared::cta.global.mbarrier::complete_tx::bytes "
                    "[%0], [%1], %2, [%3];"
                    :: "r"(smem_u32(&sbuf[k][0])),
                       "l"((const char*)(pred + c * CHUNK_ROWS * ROW_LEN)),
                       "r"((unsigned)CHUNK_BYTES),
                       "r"(smem_u32(&mbar[k])) : "memory");
            }
        }

        for (int k = 0; k < myCount; k++) {
            const int s = k & 1;
            const unsigned ph = (unsigned)((k >> 1) & 1);
            mbar_wait_parity(smem_u32(&mbar[s]), ph);

            const long long c = myStart + k;
            const long long r = c * CHUNK_ROWS + rowInChunk;

            const float* srow = &sbuf[s][rowInChunk * ROW_LEN];
            float e0, m; unsigned mi;
            scan_row([&](int i) { return srow[i]; }, sub, e0, m, mi);
            reduce_and_store(e0, m, mi, lane, sub, r, det, valid_f, valid_b, true);

            __syncthreads();   // all 8 warps done with sbuf[s]

            if (tid == 0 && k + RING_D < myCount) {
                const long long c2 = c + RING_D;
                asm volatile(
                    "mbarrier.arrive.expect_tx.shared.b64 _, [%0], %1;"
                    :: "r"(smem_u32(&mbar[s])), "r"((unsigned)CHUNK_BYTES)
                    : "memory");
                asm volatile(
                    "cp.async.bulk.shared::cta.global.mbarrier::complete_tx::bytes "
                    "[%0], [%1], %2, [%3];"
                    :: "r"(smem_u32(&sbuf[s][0])),
                       "l"((const char*)(pred + c2 * CHUNK_ROWS * ROW_LEN)),
                       "r"((unsigned)CHUNK_BYTES),
                       "r"(smem_u32(&mbar[s])) : "memory");
            }
        }
    }

    // Tail rows (total % 32): block 0 via direct LDG.
    if (bid == 0) {
        const long long tail0 = (long long)numFull * CHUNK_ROWS;
        if (tail0 < (long long)total) {
            const long long r = tail0 + rowInChunk;
            const bool wvalid = (r < (long long)total);
            const long long rr = wvalid ? r : (long long)(total - 1);
            const float* row = pred + rr * ROW_LEN;

            float e0, m; unsigned mi;
            scan_row([&](int i) { return row[i]; }, sub, e0, m, mi);
            reduce_and_store(e0, m, mi, lane, sub, r, det, valid_f, valid_b, wvalid);
        }
    }
}

extern "C" void kernel_launch(void* const* d_in, const int* in_sizes, int n_in,
                              void* d_out, int out_size)
{
    const float* pred = (const float*)d_in[0];
    const int total = in_sizes[0] / ROW_LEN;   // B*N rows
    const int numFull = total / CHUNK_ROWS;

    float* det = (float*)d_out;
    float* valid_f = nullptr;
    uint8_t* valid_b = nullptr;
    if (out_size == total * 8) {
        valid_f = det + (long long)total * 7;      // valid as 1.0/0.0 floats
    } else {
        valid_b = (uint8_t*)(det + (long long)total * 7);  // valid as bytes
    }

    int blocks = PERSIST_BLOCKS;
    if (numFull > 0 && numFull < blocks) blocks = numFull;
    if (blocks < 1) blocks = 1;
    postproc_kernel<<<blocks, 256>>>(pred, det, valid_f, valid_b, total, numFull);
}

// round 11
// speedup vs baseline: 1.2821x; 1.0763x over previous
#include <cuda_runtime.h>
#include <cstdint>

// Row layout: [x, y, w, h, obj_conf, cls_0 .. cls_79]  (85 floats per row)
// Outputs: detections [total,7] fp32, then valid [total] (fp32 1/0 or uint8).

#define ROW_LEN 85
#define CONF_THRES 0.05f

#define ROWS_PER_WARP 4
#define WARPS_PER_BLOCK 16
#define THREADS (WARPS_PER_BLOCK * 32)                     // 512
#define ROWS_PER_STAGE (ROWS_PER_WARP * WARPS_PER_BLOCK)   // 64
#define STAGES 2
#define ROWS_PER_BLOCK (ROWS_PER_STAGE * STAGES)           // 128
#define STAGE_FLOATS (ROWS_PER_STAGE * ROW_LEN)            // 5440
#define STAGE_BYTES (STAGE_FLOATS * 4)                     // 21760 (mult of 16)

__device__ __forceinline__ unsigned smem_u32(const void* p) {
    unsigned a;
    asm("{ .reg .u64 t; cvta.to.shared.u64 t, %1; cvt.u32.u64 %0, t; }"
        : "=r"(a) : "l"(p));
    return a;
}

__device__ __forceinline__ void mbar_wait_parity(unsigned addr, unsigned parity) {
    asm volatile(
        "{\n\t"
        ".reg .pred P;\n\t"
        "WAIT_%=: \n\t"
        "mbarrier.try_wait.parity.acquire.cta.shared::cta.b64 P, [%0], %1, 0x989680;\n\t"
        "@P bra.uni DONE_%=;\n\t"
        "bra.uni WAIT_%=;\n\t"
        "DONE_%=:\n\t"
        "}"
        :: "r"(addr), "r"(parity) : "memory");
}

// Scan 85 floats of one row (strided by 8 over 8 lanes), return per-lane
// (e0, max m, winning class index). Proven R3..R7 semantics.
template <typename LoadF>
__device__ __forceinline__ void scan_row(LoadF ld, int sub,
                                         float& e0, float& m, unsigned& mi) {
    e0 = ld(sub);
    m  = (sub >= 5) ? e0 : -1e30f;     // classes 0..2 live in lanes 5..7
    int wk = 0;
    #pragma unroll
    for (int k = 1; k < 10; k++) {
        float v = ld(sub + 8 * k);
        if (v > m) { m = v; wk = k; }
    }
    if (sub < ROW_LEN - 80) {          // elems 80..84
        float v = ld(sub + 80);
        if (v > m) { m = v; wk = 10; }
    }
    mi = (unsigned)(sub - 5 + 8 * wk);
}

// Group reduction + output write for one row (proven R3..R7 logic).
__device__ __forceinline__ void reduce_and_store(
    float e0, float m, unsigned mi, int lane, int sub, long long r,
    float* __restrict__ det, float* __restrict__ valid_f,
    uint8_t* __restrict__ valid_b, bool wvalid)
{
    const unsigned gmask = 0xFFu << (lane & 24);
    const unsigned mb    = __float_as_uint(m);
    const unsigned maxb  = __reduce_max_sync(gmask, mb);
    const unsigned cand  = (mb == maxb) ? mi : 0xFFFFFFFFu;
    const unsigned gidx  = __reduce_min_sync(gmask, cand);

    const float conf = __shfl_sync(0xFFFFFFFFu, e0, (lane & 24) | 4);
    const float vf   = (conf >= CONF_THRES) ? 1.0f : 0.0f;

    if (wvalid) {
        if (sub < 7) {
            float outv;
            if (sub < 5)       outv = e0 * vf;
            else if (sub == 5) outv = __uint_as_float(maxb) * vf;
            else               outv = (float)gidx * vf;
            det[r * 7 + sub] = outv;
        } else {
            if (valid_f) valid_f[r] = vf;
            else         valid_b[r] = (vf != 0.0f) ? 1 : 0;
        }
    }
}

__global__ __launch_bounds__(THREADS) void postproc_kernel(
    const float* __restrict__ pred,
    float* __restrict__ det,
    float* __restrict__ valid_f,
    uint8_t* __restrict__ valid_b,
    int total)
{
    __shared__ float sbuf[STAGES][STAGE_FLOATS];
    __shared__ __align__(8) unsigned long long mbar[STAGES];

    const int tid  = threadIdx.x;
    const int lane = tid & 31;
    const int wid  = tid >> 5;              // warp in block (0..15)
    const int sub  = lane & 7;              // lane within 8-lane group
    const int grp  = lane >> 3;             // 0..3: which of this warp's rows

    // Bank-conflict-free mapping: within a 64-row stage, warp w takes rows
    // {base + 8*grp} with base = (w&7) + 32*(w>>3). Row delta 8 gives smem
    // bank offsets {0,8,16,24} for the 4 groups (21*8 mod 32 == 8), so the
    // groups tile all 32 banks exactly.
    const int rowInStage = (wid & 7) + ((wid >> 3) << 5) + 8 * grp;

    const long long blockRow0 = (long long)blockIdx.x * ROWS_PER_BLOCK;
    const bool full_block = (blockRow0 + ROWS_PER_BLOCK <= (long long)total);

    if (full_block) {
        // ---- producer: issue both stage copies ASAP (before block sync) ----
        if (tid == 0) {
            #pragma unroll
            for (int s = 0; s < STAGES; s++) {
                asm volatile("mbarrier.init.shared.b64 [%0], %1;"
                             :: "r"(smem_u32(&mbar[s])), "r"(1u) : "memory");
            }
            asm volatile("fence.proxy.async.shared::cta;" ::: "memory");
            const char* gsrc = (const char*)(pred + blockRow0 * ROW_LEN);
            #pragma unroll
            for (int s = 0; s < STAGES; s++) {
                asm volatile(
                    "mbarrier.arrive.expect_tx.shared.b64 _, [%0], %1;"
                    :: "r"(smem_u32(&mbar[s])), "r"((unsigned)STAGE_BYTES)
                    : "memory");
                asm volatile(
                    "cp.async.bulk.shared::cta.global.mbarrier::complete_tx::bytes "
                    "[%0], [%1], %2, [%3];"
                    :: "r"(smem_u32(&sbuf[s][0])),
                       "l"(gsrc + (size_t)s * STAGE_BYTES),
                       "r"((unsigned)STAGE_BYTES),
                       "r"(smem_u32(&mbar[s])) : "memory");
            }
        }
        __syncthreads();   // mbarrier init visible to all before waiting

        // ---- consumers: each warp processes its 4 rows per stage ----
        #pragma unroll
        for (int s = 0; s < STAGES; s++) {
            mbar_wait_parity(smem_u32(&mbar[s]), 0u);

            const float* srow = &sbuf[s][rowInStage * ROW_LEN];
            float e0, m; unsigned mi;
            scan_row([&](int i) { return srow[i]; }, sub, e0, m, mi);

            const long long r = blockRow0 + s * ROWS_PER_STAGE + rowInStage;
            reduce_and_store(e0, m, mi, lane, sub, r, det, valid_f, valid_b, true);
        }
    } else {
        // ---- partial tail block: direct-LDG path (proven R3 logic) ----
        #pragma unroll 1
        for (int s = 0; s < STAGES; s++) {
            const long long r = blockRow0 + s * ROWS_PER_STAGE + rowInStage;
            const bool wvalid = (r < (long long)total);
            const long long rr = wvalid ? r : (long long)(total - 1);
            const float* row = pred + rr * ROW_LEN;

            float e0, m; unsigned mi;
            scan_row([&](int i) { return row[i]; }, sub, e0, m, mi);
            reduce_and_store(e0, m, mi, lane, sub, r, det, valid_f, valid_b, wvalid);
        }
    }
}

extern "C" void kernel_launch(void* const* d_in, const int* in_sizes, int n_in,
                              void* d_out, int out_size)
{
    const float* pred = (const float*)d_in[0];
    const int total = in_sizes[0] / ROW_LEN;   // B*N rows

    float* det = (float*)d_out;
    float* valid_f = nullptr;
    uint8_t* valid_b = nullptr;
    if (out_size == total * 8) {
        valid_f = det + (long long)total * 7;      // valid as 1.0/0.0 floats
    } else {
        valid_b = (uint8_t*)(det + (long long)total * 7);  // valid as bytes
    }

    const int blocks = (int)(((long long)total + ROWS_PER_BLOCK - 1) / ROWS_PER_BLOCK);
    postproc_kernel<<<blocks, THREADS>>>(pred, det, valid_f, valid_b, total);
}

// round 12
// speedup vs baseline: 1.3450x; 1.0491x over previous
#include <cuda_runtime.h>
#include <cstdint>

// Row layout: [x, y, w, h, obj_conf, cls_0 .. cls_79]  (85 floats per row)
// Outputs: detections [total,7] fp32, then valid [total] (fp32 1/0 or uint8).

#define ROW_LEN 85
#define CONF_THRES 0.05f

#define ROWS_PER_WARP 4
#define WARPS_PER_BLOCK 8
#define ROWS_PER_STAGE (ROWS_PER_WARP * WARPS_PER_BLOCK)   // 32
#define STAGES 2
#define ROWS_PER_BLOCK (ROWS_PER_STAGE * STAGES)           // 64
#define STAGE_FLOATS (ROWS_PER_STAGE * ROW_LEN)            // 2720
#define STAGE_BYTES (STAGE_FLOATS * 4)                     // 10880 (mult of 16)

__device__ __forceinline__ unsigned smem_u32(const void* p) {
    unsigned a;
    asm("{ .reg .u64 t; cvta.to.shared.u64 t, %1; cvt.u32.u64 %0, t; }"
        : "=r"(a) : "l"(p));
    return a;
}

__device__ __forceinline__ void mbar_wait_parity(unsigned addr, unsigned parity) {
    asm volatile(
        "{\n\t"
        ".reg .pred P;\n\t"
        "WAIT_%=: \n\t"
        "mbarrier.try_wait.parity.acquire.cta.shared::cta.b64 P, [%0], %1, 0x989680;\n\t"
        "@P bra.uni DONE_%=;\n\t"
        "bra.uni WAIT_%=;\n\t"
        "DONE_%=:\n\t"
        "}"
        :: "r"(addr), "r"(parity) : "memory");
}

// Scan 85 floats of one row (strided by 8 over 8 lanes), return per-lane
// (e0, max m, winning class index). Proven R3..R7 semantics.
template <typename LoadF>
__device__ __forceinline__ void scan_row(LoadF ld, int sub,
                                         float& e0, float& m, unsigned& mi) {
    e0 = ld(sub);
    m  = (sub >= 5) ? e0 : -1e30f;     // classes 0..2 live in lanes 5..7
    int wk = 0;
    #pragma unroll
    for (int k = 1; k < 10; k++) {
        float v = ld(sub + 8 * k);
        if (v > m) { m = v; wk = k; }
    }
    if (sub < ROW_LEN - 80) {          // elems 80..84
        float v = ld(sub + 80);
        if (v > m) { m = v; wk = 10; }
    }
    mi = (unsigned)(sub - 5 + 8 * wk);
}

// Group reduction + output write for one row (proven R3..R7 logic).
__device__ __forceinline__ void reduce_and_store(
    float e0, float m, unsigned mi, int lane, int sub, long long r,
    float* __restrict__ det, float* __restrict__ valid_f,
    uint8_t* __restrict__ valid_b, bool wvalid)
{
    const unsigned gmask = 0xFFu << (lane & 24);
    const unsigned mb    = __float_as_uint(m);
    const unsigned maxb  = __reduce_max_sync(gmask, mb);
    const unsigned cand  = (mb == maxb) ? mi : 0xFFFFFFFFu;
    const unsigned gidx  = __reduce_min_sync(gmask, cand);

    const float conf = __shfl_sync(0xFFFFFFFFu, e0, (lane & 24) | 4);
    const float vf   = (conf >= CONF_THRES) ? 1.0f : 0.0f;

    if (wvalid) {
        if (sub < 7) {
            float outv;
            if (sub < 5)       outv = e0 * vf;
            else if (sub == 5) outv = __uint_as_float(maxb) * vf;
            else               outv = (float)gidx * vf;
            det[r * 7 + sub] = outv;
        } else {
            if (valid_f) valid_f[r] = vf;
            else         valid_b[r] = (vf != 0.0f) ? 1 : 0;
        }
    }
}

__global__ __launch_bounds__(256) void postproc_kernel(
    const float* __restrict__ pred,
    float* __restrict__ det,
    float* __restrict__ valid_f,
    uint8_t* __restrict__ valid_b,
    int total)
{
    __shared__ float sbuf[STAGES][STAGE_FLOATS];
    __shared__ __align__(8) unsigned long long mbar[STAGES];

    const int tid  = threadIdx.x;
    const int lane = tid & 31;
    const int wid  = tid >> 5;              // warp in block
    const int sub  = lane & 7;              // lane within 8-lane group
    const int grp  = lane >> 3;             // 0..3: which of this warp's rows

    // Bank-conflict-free mapping: warp wid handles rows {wid + 8*grp} within
    // each 32-row stage (row delta 8 -> the 4 groups tile all 32 banks).
    const int rowInStage = wid + 8 * grp;

    const long long blockRow0 = (long long)blockIdx.x * ROWS_PER_BLOCK;
    const bool full_block = (blockRow0 + ROWS_PER_BLOCK <= (long long)total);

    if (full_block) {
        // ---- producer: tid0 inits mbarriers and issues both stage copies
        //      immediately (program-order within tid0 guarantees init-before-
        //      copy; other threads only touch mbar after __syncthreads).
        if (tid == 0) {
            #pragma unroll
            for (int s = 0; s < STAGES; s++) {
                asm volatile("mbarrier.init.shared.b64 [%0], %1;"
                             :: "r"(smem_u32(&mbar[s])), "r"(1u) : "memory");
            }
            asm volatile("fence.proxy.async.shared::cta;" ::: "memory");
            const char* gsrc = (const char*)(pred + blockRow0 * ROW_LEN);
            #pragma unroll
            for (int s = 0; s < STAGES; s++) {
                asm volatile(
                    "mbarrier.arrive.expect_tx.shared.b64 _, [%0], %1;"
                    :: "r"(smem_u32(&mbar[s])), "r"((unsigned)STAGE_BYTES)
                    : "memory");
                asm volatile(
                    "cp.async.bulk.shared::cta.global.mbarrier::complete_tx::bytes "
                    "[%0], [%1], %2, [%3];"
                    :: "r"(smem_u32(&sbuf[s][0])),
                       "l"(gsrc + (size_t)s * STAGE_BYTES),
                       "r"((unsigned)STAGE_BYTES),
                       "r"(smem_u32(&mbar[s])) : "memory");
            }
        }
        __syncthreads();   // mbarrier init visible to all before waiting

        // ---- consumers: each warp processes its 4 rows per stage ----
        #pragma unroll
        for (int s = 0; s < STAGES; s++) {
            mbar_wait_parity(smem_u32(&mbar[s]), 0u);

            const float* srow = &sbuf[s][rowInStage * ROW_LEN];
            float e0, m; unsigned mi;
            scan_row([&](int i) { return srow[i]; }, sub, e0, m, mi);

            const long long r = blockRow0 + s * ROWS_PER_STAGE + rowInStage;
            reduce_and_store(e0, m, mi, lane, sub, r, det, valid_f, valid_b, true);
        }
    } else {
        // ---- partial tail block: direct-LDG path (proven R3 logic) ----
        #pragma unroll 1
        for (int s = 0; s < STAGES; s++) {
            const long long r = blockRow0 + s * ROWS_PER_STAGE + rowInStage;
            const bool wvalid = (r < (long long)total);
            const long long rr = wvalid ? r : (long long)(total - 1);
            const float* row = pred + rr * ROW_LEN;

            float e0, m; unsigned mi;
            scan_row([&](int i) { return row[i]; }, sub, e0, m, mi);
            reduce_and_store(e0, m, mi, lane, sub, r, det, valid_f, valid_b, wvalid);
        }
    }
}

extern "C" void kernel_launch(void* const* d_in, const int* in_sizes, int n_in,
                              void* d_out, int out_size)
{
    const float* pred = (const float*)d_in[0];
    const int total = in_sizes[0] / ROW_LEN;   // B*N rows

    float* det = (float*)d_out;
    float* valid_f = nullptr;
    uint8_t* valid_b = nullptr;
    if (out_size == total * 8) {
        valid_f = det + (long long)total * 7;      // valid as 1.0/0.0 floats
    } else {
        valid_b = (uint8_t*)(det + (long long)total * 7);  // valid as bytes
    }

    const int blocks = (int)(((long long)total + ROWS_PER_BLOCK - 1) / ROWS_PER_BLOCK);
    postproc_kernel<<<blocks, 256>>>(pred, det, valid_f, valid_b, total);
}